// round 3
// baseline (speedup 1.0000x reference)
#include <cuda_runtime.h>
#include <math_constants.h>

// ---------------------------------------------------------------------------
// PointNetConv: 3x (1x1 conv -> BN(train) -> ReLU) -> max over K neighbors
//   input  agg_feat [16384 nodes, K=64, C=67] flattened rows p = node*64 + k
//   L0: 67->64, L1: 64->64, L2: 64->128, out [16384, 128]
//
// Round-2 changes vs round-1:
//  * inner GEMM uses packed fma.rn.f32x2 along the channel axis (2x fp32 FMA
//    throughput; contiguous 64-bit LDS for both operands, no packing movs)
//  * layer-2 output (537MB x2 traffic) eliminated: block tile = 2 nodes, so
//    per-node max AND min over K are reduced in-smem and only [16384,128]
//    max/min (16MB) is written. Final affine picks max if a>0 else min.
// ---------------------------------------------------------------------------

#define TOTAL_ROWS (16384 * 64)           // 1,048,576 positions
#define ROWS_PB    128
#define NBLK       (TOTAL_ROWS / ROWS_PB) // 8192
#define NNODES     16384
#define EPS        1e-5f
#define PCOUNT     ((float)TOTAL_ROWS)

// ------------------------- static device scratch ---------------------------
__device__ float g_h0[TOTAL_ROWS * 64];    // raw conv0 out (268 MB)
__device__ float g_h1[TOTAL_ROWS * 64];    // raw conv1 out (268 MB)
__device__ float g_mx[NNODES * 128];       // per-node max of raw conv2 (8 MB)
__device__ float g_mn[NNODES * 128];       // per-node min of raw conv2 (8 MB)
__device__ float g_psum[128 * NBLK];
__device__ float g_psq [128 * NBLK];
__device__ float g_bna[128];
__device__ float g_bnc[128];

// packed fp32x2 fused multiply-add: d.lo += a.lo*b.lo ; d.hi += a.hi*b.hi
static __device__ __forceinline__ void ffma2(unsigned long long& d,
                                             unsigned long long a,
                                             unsigned long long b) {
    asm("fma.rn.f32x2 %0, %1, %2, %0;" : "+l"(d) : "l"(a), "l"(b));
}
static __device__ __forceinline__ float lo32(unsigned long long v) {
    return __uint_as_float((unsigned)(v & 0xffffffffull));
}
static __device__ __forceinline__ float hi32(unsigned long long v) {
    return __uint_as_float((unsigned)(v >> 32));
}

// ---------------------------------------------------------------------------
// Fused GEMM (tile 128 rows x 64 cols) + optional input BN/ReLU + per-channel
// stats partials. COUT per block is always 64; layer 2 uses gridDim.y = 2
// column halves (ob = blockIdx.y*64 selects W/B rows and output channels).
//   H[p, o] = B[o] + sum_c W[o,c] * act(X[p,c]),  act = BN_IN ? relu(a*x+c) : x
// If REDUCE: no H store; per-node (2 nodes per tile) max/min written instead.
// Thread map: rg = tid>>4 (8 rows each), cg = tid&15 (cols cg+16j, j<4).
// ---------------------------------------------------------------------------
template <int CIN, bool BN_IN, bool REDUCE>
__global__ void __launch_bounds__(256) gemm_f32x2(
    const float* __restrict__ X,
    const float* __restrict__ W,
    const float* __restrict__ B,
    const float* __restrict__ bna,
    const float* __restrict__ bnc,
    float* __restrict__ H,          // used if !REDUCE (row stride 64)
    float* __restrict__ mxout,      // used if REDUCE  [node*128 + ob + o]
    float* __restrict__ mnout,
    float* __restrict__ psum,
    float* __restrict__ psq)
{
    constexpr int SXP  = (CIN & 1) ? CIN + 3 : CIN + 2;  // 67->70, 64->66
    constexpr int CINP = (CIN & 1) ? CIN + 1 : CIN;      // 68, 64
    constexpr int TN   = 4;

    extern __shared__ float smem[];
    float* Xs = smem;                   // 128 * SXP
    float* Ws = Xs + ROWS_PB * SXP;     // 64 * SXP
    float* Bs = Ws + 64 * SXP;          // 64
    float* Ba = Bs + 64;                // CIN (if BN_IN)
    float* Bc = Ba + (BN_IN ? CIN : 0);

    const int tid = threadIdx.x;
    const int rg  = tid >> 4;
    const int cg  = tid & 15;
    const int bx  = blockIdx.x;
    const int ob  = blockIdx.y * 64;    // output-channel base
    const long long row0 = (long long)bx * ROWS_PB;

    // ---- W tile + bias + BN params ----
    for (int idx = tid; idx < 64 * CIN; idx += 256) {
        int o = idx / CIN, c = idx - o * CIN;
        Ws[o * SXP + c] = W[(ob + o) * CIN + c];
    }
    if (tid < 64) Bs[tid] = B[ob + tid];
    if (BN_IN && tid < CIN) { Ba[tid] = bna[tid]; Bc[tid] = bnc[tid]; }
    if (CINP > CIN) {   // zero the pad column read by the last c-pair
        for (int o = tid; o < 64; o += 256) Ws[o * SXP + CIN] = 0.0f;
        for (int r = tid; r < ROWS_PB; r += 256) Xs[r * SXP + CIN] = 0.0f;
    }
    if (BN_IN) __syncthreads();   // Ba/Bc needed by the X-load loop below

    // ---- X tile: flat vectorized load (block rows are contiguous) ----
    {
        const float4* Xv = (const float4*)(X + row0 * CIN);
        constexpr int NV = ROWS_PB * CIN / 4;   // 2144 or 2048
        for (int idx = tid; idx < NV; idx += 256) {
            float4 v4 = Xv[idx];
            float vv[4] = {v4.x, v4.y, v4.z, v4.w};
#pragma unroll
            for (int u = 0; u < 4; u++) {
                int e = idx * 4 + u;
                int r = e / CIN, c = e - r * CIN;
                float v = vv[u];
                if (BN_IN) v = fmaxf(fmaf(Ba[c], v, Bc[c]), 0.0f);
                Xs[r * SXP + c] = v;
            }
        }
    }
    __syncthreads();

    // ---- register-tiled GEMM, packed along channel pairs ----
    unsigned long long acc2[8][TN];
#pragma unroll
    for (int i = 0; i < 8; i++)
#pragma unroll
        for (int j = 0; j < TN; j++) acc2[i][j] = 0ull;

#pragma unroll 4
    for (int c = 0; c < CINP; c += 2) {
        unsigned long long xv[8], wv[TN];
#pragma unroll
        for (int i = 0; i < 8; i++)
            xv[i] = *reinterpret_cast<const unsigned long long*>(
                        &Xs[(rg * 8 + i) * SXP + c]);
#pragma unroll
        for (int j = 0; j < TN; j++)
            wv[j] = *reinterpret_cast<const unsigned long long*>(
                        &Ws[(cg + 16 * j) * SXP + c]);
#pragma unroll
        for (int i = 0; i < 8; i++)
#pragma unroll
            for (int j = 0; j < TN; j++)
                ffma2(acc2[i][j], xv[i], wv[j]);
    }

    // ---- epilogue ----
    float ps[TN], pq[TN], mx[TN], mn[TN];
#pragma unroll
    for (int j = 0; j < TN; j++) {
        ps[j] = 0.0f; pq[j] = 0.0f;
        mx[j] = -CUDART_INF_F; mn[j] = CUDART_INF_F;
    }

#pragma unroll
    for (int i = 0; i < 8; i++) {
        long long r = row0 + rg * 8 + i;
#pragma unroll
        for (int j = 0; j < TN; j++) {
            int o = cg + 16 * j;
            float v = lo32(acc2[i][j]) + hi32(acc2[i][j]) + Bs[o];
            if (!REDUCE) H[r * 64 + o] = v;
            ps[j] += v;
            pq[j] += v * v;
            if (REDUCE) { mx[j] = fmaxf(mx[j], v); mn[j] = fminf(mn[j], v); }
        }
    }

    // ---- deterministic block reduction of stats partials (reuse Xs) ----
    __syncthreads();
    float* Rs = Xs;                // [16][64]
    float* Rq = Xs + 16 * 64;      // [16][64]
#pragma unroll
    for (int j = 0; j < TN; j++) {
        int o = cg + 16 * j;
        Rs[rg * 64 + o] = ps[j];
        Rq[rg * 64 + o] = pq[j];
    }
    __syncthreads();
#pragma unroll
    for (int s = 8; s > 0; s >>= 1) {
        if (rg < s) {
#pragma unroll
            for (int j = 0; j < TN; j++) {
                int o = cg + 16 * j;
                Rs[rg * 64 + o] += Rs[(rg + s) * 64 + o];
                Rq[rg * 64 + o] += Rq[(rg + s) * 64 + o];
            }
        }
        __syncthreads();
    }
    if (rg == 0) {
#pragma unroll
        for (int j = 0; j < TN; j++) {
            int o = cg + 16 * j;
            psum[(ob + o) * NBLK + bx] = Rs[o];
            psq [(ob + o) * NBLK + bx] = Rq[o];
        }
    }

    // ---- per-node max/min reduction (tile = exactly 2 nodes) ----
    if (REDUCE) {
        __syncthreads();           // Rs/Rq done; reuse Xs again
        float* Mx = Xs;            // [16][64]
        float* Mn = Xs + 16 * 64;  // [16][64]
#pragma unroll
        for (int j = 0; j < TN; j++) {
            int o = cg + 16 * j;
            Mx[rg * 64 + o] = mx[j];
            Mn[rg * 64 + o] = mn[j];
        }
        __syncthreads();
#pragma unroll
        for (int s = 4; s > 0; s >>= 1) {
            if ((rg & 7) < s) {
#pragma unroll
                for (int j = 0; j < TN; j++) {
                    int o = cg + 16 * j;
                    Mx[rg * 64 + o] = fmaxf(Mx[rg * 64 + o], Mx[(rg + s) * 64 + o]);
                    Mn[rg * 64 + o] = fminf(Mn[rg * 64 + o], Mn[(rg + s) * 64 + o]);
                }
            }
            __syncthreads();
        }
        if ((rg & 7) == 0) {       // rg==0 -> node A, rg==8 -> node B
            int node = bx * 2 + (rg >> 3);
#pragma unroll
            for (int j = 0; j < TN; j++) {
                int o = cg + 16 * j;
                mxout[node * 128 + ob + o] = Mx[rg * 64 + o];
                mnout[node * 128 + ob + o] = Mn[rg * 64 + o];
            }
        }
    }
}

// ---------------------------------------------------------------------------
// Finalize stats: one block per channel -> affine a = g*rsqrt(var+eps),
// c = beta - mean*a
// ---------------------------------------------------------------------------
__global__ void __launch_bounds__(256) stats_finalize(
    const float* __restrict__ psum, const float* __restrict__ psq,
    const float* __restrict__ gamma, const float* __restrict__ beta,
    float* __restrict__ bna, float* __restrict__ bnc)
{
    const int o = blockIdx.x;
    const int tid = threadIdx.x;
    float s = 0.0f, q = 0.0f;
    for (int b = tid; b < NBLK; b += 256) {
        s += psum[o * NBLK + b];
        q += psq [o * NBLK + b];
    }
    __shared__ float sh[512];
    sh[tid] = s; sh[256 + tid] = q;
    __syncthreads();
    for (int st = 128; st > 0; st >>= 1) {
        if (tid < st) {
            sh[tid]       += sh[tid + st];
            sh[256 + tid] += sh[256 + tid + st];
        }
        __syncthreads();
    }
    if (tid == 0) {
        float mean = sh[0] / PCOUNT;
        float var  = sh[256] / PCOUNT - mean * mean;
        float a    = gamma[o] * rsqrtf(var + EPS);
        bna[o] = a;
        bnc[o] = beta[o] - mean * a;
    }
}

// ---------------------------------------------------------------------------
// Final: out[node,c] = relu(a*(a>0 ? max : min) + c)   (affine is monotone)
// ---------------------------------------------------------------------------
__global__ void __launch_bounds__(256) apply_out(
    const float* __restrict__ mx, const float* __restrict__ mn,
    const float* __restrict__ bna, const float* __restrict__ bnc,
    float* __restrict__ out)
{
    int idx = blockIdx.x * 256 + threadIdx.x;   // [0, 16384*128)
    int c = idx & 127;
    float a = bna[c];
    float h = (a > 0.0f) ? mx[idx] : mn[idx];
    out[idx] = fmaxf(fmaf(a, h, bnc[c]), 0.0f);
}

// ---------------------------------------------------------------------------
static constexpr int smem_bytes(int cin, bool bn) {
    int sxp = (cin & 1) ? cin + 3 : cin + 2;
    int fl = ROWS_PB * sxp + 64 * sxp + 64 + (bn ? 2 * cin : 0);
    return fl * 4;
}

extern "C" void kernel_launch(void* const* d_in, const int* in_sizes, int n_in,
                              void* d_out, int out_size)
{
    const float* x   = (const float*)d_in[0];
    const float* w0  = (const float*)d_in[1];
    const float* b0  = (const float*)d_in[2];
    const float* gm0 = (const float*)d_in[3];
    const float* be0 = (const float*)d_in[4];
    const float* w1  = (const float*)d_in[5];
    const float* b1  = (const float*)d_in[6];
    const float* gm1 = (const float*)d_in[7];
    const float* be1 = (const float*)d_in[8];
    const float* w2  = (const float*)d_in[9];
    const float* b2  = (const float*)d_in[10];
    const float* gm2 = (const float*)d_in[11];
    const float* be2 = (const float*)d_in[12];
    float* out = (float*)d_out;

    float *h0, *h1, *mx, *mn, *psum, *psq, *bna, *bnc;
    cudaGetSymbolAddress((void**)&h0,   g_h0);
    cudaGetSymbolAddress((void**)&h1,   g_h1);
    cudaGetSymbolAddress((void**)&mx,   g_mx);
    cudaGetSymbolAddress((void**)&mn,   g_mn);
    cudaGetSymbolAddress((void**)&psum, g_psum);
    cudaGetSymbolAddress((void**)&psq,  g_psq);
    cudaGetSymbolAddress((void**)&bna,  g_bna);
    cudaGetSymbolAddress((void**)&bnc,  g_bnc);

    constexpr int S0 = smem_bytes(67, false);
    constexpr int S1 = smem_bytes(64, true);
    constexpr int S2 = smem_bytes(64, true);
    cudaFuncSetAttribute(gemm_f32x2<67, false, false>,
                         cudaFuncAttributeMaxDynamicSharedMemorySize, S0);
    cudaFuncSetAttribute(gemm_f32x2<64, true, false>,
                         cudaFuncAttributeMaxDynamicSharedMemorySize, S1);
    cudaFuncSetAttribute(gemm_f32x2<64, true, true>,
                         cudaFuncAttributeMaxDynamicSharedMemorySize, S2);

    // L0: conv(67->64) + stats
    gemm_f32x2<67, false, false><<<dim3(NBLK, 1), 256, S0>>>(
        x, w0, b0, nullptr, nullptr, h0, nullptr, nullptr, psum, psq);
    stats_finalize<<<64, 256>>>(psum, psq, gm0, be0, bna, bnc);

    // L1: bn0+relu (on load) -> conv(64->64) + stats
    gemm_f32x2<64, true, false><<<dim3(NBLK, 1), 256, S1>>>(
        h0, w1, b1, bna, bnc, h1, nullptr, nullptr, psum, psq);
    stats_finalize<<<64, 256>>>(psum, psq, gm1, be1, bna, bnc);

    // L2: bn1+relu (on load) -> conv(64->128, two col halves) + stats
    //     + in-block per-node max/min (no H2 materialization)
    gemm_f32x2<64, true, true><<<dim3(NBLK, 2), 256, S2>>>(
        h1, w2, b2, bna, bnc, nullptr, mx, mn, psum, psq);
    stats_finalize<<<128, 256>>>(psum, psq, gm2, be2, bna, bnc);

    // bn2 affine + max-over-K via max/min select + relu
    apply_out<<<(NNODES * 128) / 256, 256>>>(mx, mn, bna, bnc, out);
}